// round 15
// baseline (speedup 1.0000x reference)
#include <cuda_runtime.h>
#include <cuda_fp16.h>
#include <math.h>
#include <stdint.h>

// SOMFNN: two layers of (ALMMo codebook lamb) + sigmoid(Linear)
// stau = base/2 (scalar); prototypes are input samples -> all distances from
// Gram = X X^T; min-distance-over-all-predecessors shortcut for new rules.
// GEMMs: fp16 mma.sync.m16n8k16 (fp32 accum), SW128-swizzled smem.
// r15: 3-stage cp.async pipeline (96KB smem) -- tile-boundary copy latency
// off the critical path. Everything else identical to r14.

#define MAXN 2048
#define MAXD 2048
#define NCHUNK 32
#define NCONV 512
#define GEMM_SMEM 98304

__device__ float g_G0[(size_t)MAXN * MAXN];
__device__ float g_G1[(size_t)MAXN * MAXN];
__device__ float g_H[(size_t)MAXN * MAXD];
__device__ __half g_Ah[(size_t)MAXN * MAXD];
__device__ __half g_Bh[(size_t)MAXN * MAXD];
__device__ __half g_Hh[(size_t)MAXN * MAXD];
__device__ float g_SEN[2][MAXN];
__device__ float g_colpart[NCHUNK][MAXD];
__device__ float g_base[2][2];
__device__ unsigned g_mindu[2][MAXN];
__device__ int   g_rules[2][MAXN];
__device__ int   g_protos[2][MAXN];
__device__ int   g_count[2];

// order-preserving float<->unsigned encoding (monotone; min exact)
__device__ __forceinline__ unsigned encf(float f) {
    unsigned u = __float_as_uint(f);
    return (u & 0x80000000u) ? ~u : (u | 0x80000000u);
}
__device__ __forceinline__ float decf(unsigned e) {
    unsigned u = (e & 0x80000000u) ? (e ^ 0x80000000u) : ~e;
    return __uint_as_float(u);
}

__device__ __forceinline__ float blockReduceSum(float v) {
    __shared__ float sh[32];
    int lane = threadIdx.x & 31, wid = threadIdx.x >> 5;
#pragma unroll
    for (int o = 16; o; o >>= 1) v += __shfl_down_sync(0xffffffffu, v, o);
    __syncthreads();
    if (lane == 0) sh[wid] = v;
    __syncthreads();
    if (wid == 0) {
        int nw = (blockDim.x + 31) >> 5;
        v = (lane < nw) ? sh[lane] : 0.0f;
#pragma unroll
        for (int o = 16; o; o >>= 1) v += __shfl_down_sync(0xffffffffu, v, o);
    }
    return v;
}

// ---------------- sequential rule-creation scan (device fn, 1 warp) --------
__device__ void scan_dev(const float* G, const float* sen,
                         const unsigned* mindu, const float* base,
                         int* rules, int* protos, int* count, int N) {
    const int lane = threadIdx.x & 31;
    const float DELTA = 0.13533528323661270f;  // exp(-2)
    float stau = base[1];
    bool st_ok = (stau > 0.0f) && (stau < 3.0e38f);
    float thr2 = 2.0f * stau;
    int cnt = 0;

    for (int i0 = 0; i0 < N; i0 += 32) {
        int lim = (N - i0 < 32) ? (N - i0) : 32;
        int myi = i0 + lane;
        bool cert = false;
        if (myi < N && st_ok)
            cert = (decf(mindu[myi]) > thr2);   // exp(-mind/stau) < e^-2
        unsigned mask = __ballot_sync(0xffffffffu, cert);
        unsigned need = (lim == 32) ? 0xffffffffu : ((1u << lim) - 1u);
        if ((mask & need) == need) {
            if (lane < lim) {
                rules[myi] = cnt + lane;
                protos[cnt + lane] = myi;
            }
            cnt += lim;
            continue;
        }
        for (int t = 0; t < lim; t++) {
            int i = i0 + t;
            bool newr;
            int slot = 0;
            if (cnt == 0 || ((mask >> t) & 1u)) {
                newr = true;
            } else {
                float si = sen[i];
                const float* Gi = G + (size_t)i * N;
                float best = -INFINITY;
                int bestr = 0x7fffffff;
                for (int rr = lane; rr < cnt; rr += 32) {
                    int pr = protos[rr];
                    float dd = si + sen[pr] - 2.0f * Gi[pr];
                    float dens = __expf(-dd / stau);
                    if (dens > best) { best = dens; bestr = rr; }
                }
#pragma unroll
                for (int off = 16; off; off >>= 1) {
                    float ob = __shfl_down_sync(0xffffffffu, best, off);
                    int obr = __shfl_down_sync(0xffffffffu, bestr, off);
                    if (ob > best || (ob == best && obr < bestr)) { best = ob; bestr = obr; }
                }
                best  = __shfl_sync(0xffffffffu, best, 0);
                bestr = __shfl_sync(0xffffffffu, bestr, 0);
                newr = (best < DELTA);
                slot = bestr;
            }
            if (newr) slot = cnt;
            if (lane == 0) rules[i] = slot;
            if (newr) {
                if (lane == 0) protos[cnt] = i;
                cnt++;
            }
        }
    }
    if (lane == 0) count[0] = cnt;
}

// ---------------- block-level scan with parallel-certs fast path ------------
__device__ void scan_block(const float* G, const float* sen,
                           const unsigned* mindu, const float* base,
                           int* rules, int* protos, int* count, int N) {
    __shared__ int anyfail;
    const int tid = threadIdx.x;
    float stau = base[1];
    bool st_ok = (stau > 0.0f) && (stau < 3.0e38f);
    float thr2 = 2.0f * stau;
    if (tid == 0) anyfail = 0;
    __syncthreads();
    for (int i = tid; i < N; i += 256) {
        bool cert = st_ok && (decf(mindu[i]) > thr2);
        if (!cert) anyfail = 1;
    }
    __syncthreads();
    if (!anyfail) {
        for (int i = tid; i < N; i += 256) {
            rules[i] = i;
            protos[i] = i;
        }
        if (tid == 0) count[0] = N;
    } else if (tid < 32) {
        scan_dev(G, sen, mindu, base, rules, protos, count, N);
    }
}

// ---------------- fused aux kernel (role-split grid) -------------------------
// role order: [scan prev (0/1)] [mindinit] [rowstats: convert+rowsumsq]
//             [convert W] [colsum X]
__global__ void fused_aux_kernel(
    const float* __restrict__ X, __half* __restrict__ Xh, int N, int K,
    const float* __restrict__ W, __half* __restrict__ Wh, int WM,
    float* __restrict__ sen, unsigned* __restrict__ minduInit,
    const float* Gprev, const float* senPrev, const unsigned* minduPrev,
    const float* basePrev, int* rulesPrev, int* protosPrev, int* countPrev,
    int Nprev)
{
    int bid = blockIdx.x;
    const int tid = threadIdx.x;

    const int nScan = Gprev ? 1 : 0;
    if (bid < nScan) {
        scan_block(Gprev, senPrev, minduPrev, basePrev,
                   rulesPrev, protosPrev, countPrev, Nprev);
        return;
    }
    bid -= nScan;

    const int nMind = N >> 8;
    if (bid < nMind) {
        minduInit[bid * 256 + tid] = 0xFF800000u;   // encf(+inf)
        return;
    }
    bid -= nMind;

    if (bid < N) {   // rowstats: one block per row; convert (opt) + sumsq
        const float4* row = (const float4*)(X + (size_t)bid * K);
        __half2* drow = Xh ? (__half2*)(Xh + (size_t)bid * K) : nullptr;
        float s = 0.0f;
        const int k4 = K >> 2;
#pragma unroll 4
        for (int k = tid; k < k4; k += 256) {
            float4 v = row[k];
            s += v.x * v.x + v.y * v.y + v.z * v.z + v.w * v.w;
            if (drow) {
                drow[2 * k]     = __floats2half2_rn(v.x, v.y);
                drow[2 * k + 1] = __floats2half2_rn(v.z, v.w);
            }
        }
        s = blockReduceSum(s);
        if (tid == 0) sen[bid] = s;
        return;
    }
    bid -= N;

    const int nConvW = Wh ? NCONV : 0;
    if (bid < nConvW) {
        int n4 = (WM * K) >> 2;
#pragma unroll 2
        for (int i = bid * 256 + tid; i < n4; i += nConvW * 256) {
            float4 v = ((const float4*)W)[i];
            __half2* d = (__half2*)Wh + 2 * i;
            d[0] = __floats2half2_rn(v.x, v.y);
            d[1] = __floats2half2_rn(v.z, v.w);
        }
        return;
    }
    bid -= nConvW;

    {   // colsum chunks, 4-row unroll (same summation order)
        int chunk = bid / (K >> 8);
        int cseg = bid % (K >> 8);
        int c = cseg * 256 + tid;
        int r0 = chunk * (N / NCHUNK), r1 = r0 + N / NCHUNK;
        float s = 0.0f;
        int i = r0;
        for (; i + 4 <= r1; i += 4) {
            float a0 = X[(size_t)i * K + c];
            float a1 = X[(size_t)(i + 1) * K + c];
            float a2 = X[(size_t)(i + 2) * K + c];
            float a3 = X[(size_t)(i + 3) * K + c];
            s += a0; s += a1; s += a2; s += a3;
        }
        for (; i < r1; i++) s += X[(size_t)i * K + c];
        g_colpart[chunk][c] = s;
    }
}

// ---------------- tensor-core helpers ----------------
__device__ __forceinline__ unsigned smaddr(const void* p) {
    unsigned r;
    asm("{.reg .u64 t; cvta.to.shared.u64 t, %1; cvt.u32.u64 %0, t;}"
        : "=r"(r) : "l"(p));
    return r;
}

__device__ __forceinline__ void ldsm4(unsigned& r0, unsigned& r1, unsigned& r2,
                                      unsigned& r3, unsigned a) {
    asm volatile("ldmatrix.sync.aligned.m8n8.x4.shared.b16 {%0,%1,%2,%3},[%4];"
                 : "=r"(r0), "=r"(r1), "=r"(r2), "=r"(r3) : "r"(a));
}

__device__ __forceinline__ void mma_f16(float* c, const unsigned* a,
                                        unsigned b0, unsigned b1) {
    asm volatile(
        "mma.sync.aligned.m16n8k16.row.col.f32.f16.f16.f32 "
        "{%0,%1,%2,%3},{%4,%5,%6,%7},{%8,%9},{%0,%1,%2,%3};"
        : "+f"(c[0]), "+f"(c[1]), "+f"(c[2]), "+f"(c[3])
        : "r"(a[0]), "r"(a[1]), "r"(a[2]), "r"(a[3]), "r"(b0), "r"(b1));
}

__device__ __forceinline__ void cpa16(unsigned dst, const void* src) {
    asm volatile("cp.async.cg.shared.global [%0], [%1], 16;"
                 :: "r"(dst), "l"(src));
}
__device__ __forceinline__ void cpa_commit() {
    asm volatile("cp.async.commit_group;");
}
__device__ __forceinline__ void cpa_wait0() {
    asm volatile("cp.async.wait_group 0;");
}
__device__ __forceinline__ void cpa_wait1() {
    asm volatile("cp.async.wait_group 1;");
}

__device__ __forceinline__ float fsigmoid(float s) {
    return 1.0f / (1.0f + __expf(-s));
}

// ---------------- lamb (density normalization) device fn -------------------
__device__ void lamb_dev(int n, const float* G, const float* sen,
                         const int* rules, const int* protos, int count,
                         float stau, float* out, int N) {
    float sn = sen[n];
    float inv = -1.0f / stau;
    const float* Gn = G + (size_t)n * N;
    float s = 0.0f;
    for (int r = threadIdx.x; r < count; r += blockDim.x) {
        int pr = protos[r];
        float d = sn + sen[pr] - 2.0f * Gn[pr];
        s += __expf(d * inv);
    }
    s = blockReduceSum(s);
    if (threadIdx.x == 0) {
        int pr = protos[rules[n]];
        float d = sn + sen[pr] - 2.0f * Gn[pr];
        out[n] = __expf(d * inv) / s;
    }
}

// ---------------- base role (1 block, 256 threads) -------------------------
__device__ void base_dev(const float* sen, float* baseout, int N, int K) {
    float invN = 1.0f / (float)N;
    float s1 = 0.0f, s2 = 0.0f;
    for (int i = threadIdx.x; i < N; i += 256) s1 += sen[i];
    for (int c = threadIdx.x; c < K; c += 256) {
        float cs = 0.0f;
#pragma unroll
        for (int h = 0; h < NCHUNK; h++) cs += g_colpart[h][c];
        float m = cs * invN;
        s2 += m * m;
    }
    s1 = blockReduceSum(s1);
    __syncthreads();
    s2 = blockReduceSum(s2);
    if (threadIdx.x == 0) {
        float base = s1 * invN - s2;
        baseout[0] = base;
        baseout[1] = 0.5f * base;
    }
}

// ---------------- MEGA GEMM: gram || linear || lamb(prev) || base ----------
__global__ void __launch_bounds__(256, 2)
mega_gemm_kernel(const __half* __restrict__ Agr, float* __restrict__ G,
                 int Ng, int Kg, const float* __restrict__ sen,
                 unsigned* __restrict__ mindu, int triCount,
                 const __half* __restrict__ Al, const __half* __restrict__ Bl,
                 float* __restrict__ Cl, __half* __restrict__ Chl,
                 const float* __restrict__ bias, int Nl, int Kl,
                 float* __restrict__ baseOut,
                 const float* __restrict__ lambG,
                 const float* __restrict__ lambSen,
                 const float* __restrict__ lambBase,
                 const int* __restrict__ lambRules,
                 const int* __restrict__ lambProtos,
                 const int* __restrict__ lambCount,
                 float* __restrict__ lambOut, int lambN) {
    extern __shared__ char sm[];
    const int tid = threadIdx.x, wid = tid >> 5, lane = tid & 31;

    const int linCount = (Ng >> 7) * (Nl >> 7);
    const int nb = triCount + linCount;
    if ((int)blockIdx.x == nb + lambN) {
        base_dev(sen, baseOut, Ng, Kg);   // base for CURRENT layer
        return;
    }
    if ((int)blockIdx.x >= nb) {
        int n = blockIdx.x - nb;
        lamb_dev(n, lambG, lambSen, lambRules, lambProtos, lambCount[0],
                 lambBase[1], lambOut, lambN);
        return;
    }

    const __half *A, *B;
    float* C;
    __half* Ch;
    int NC, K, mode, bi, bj;
    if ((int)blockIdx.x < triCount) {
        int id = blockIdx.x;
        bi = (int)((sqrtf(8.0f * (float)id + 1.0f) - 1.0f) * 0.5f);
        while ((bi + 1) * (bi + 2) / 2 <= id) bi++;
        while (bi * (bi + 1) / 2 > id) bi--;
        bj = id - bi * (bi + 1) / 2;
        A = Agr; B = Agr; C = G; Ch = nullptr; NC = Ng; K = Kg; mode = 2;
    } else {
        int lid = blockIdx.x - triCount;
        int nbx = Nl >> 7;
        bi = lid / nbx; bj = lid % nbx;
        A = Al; B = Bl; C = Cl; Ch = Chl; NC = Nl; K = Kl; mode = 1;
    }
    const int rowBase = bi << 7, colBase = bj << 7;

    const int r = tid >> 1;
    const int hh = tid & 1;
    const __half* Ag = A + (size_t)(rowBase + r) * K + hh * 32;
    const __half* Bg = B + (size_t)(colBase + r) * K + hh * 32;
    unsigned stsOff[4];
#pragma unroll
    for (int j = 0; j < 4; j++)
        stsOff[j] = (unsigned)(r * 128 + ((((hh << 2) + j) ^ (r & 7)) << 4));

    const int wm = (wid & 3) << 5, wn = (wid >> 2) << 6;
    const int aRow = wm + ((lane >> 3) & 1) * 8 + (lane & 7);
    const int aQ = lane >> 4;
    const int bRow = wn + (lane >> 4) * 8 + (lane & 7);
    const int bQ = (lane >> 3) & 1;

    const unsigned smBase = smaddr(sm);

    float acc[2][8][4];
#pragma unroll
    for (int fm = 0; fm < 2; fm++)
#pragma unroll
        for (int fn = 0; fn < 8; fn++)
#pragma unroll
            for (int q = 0; q < 4; q++) acc[fm][fn][q] = 0.0f;

    const int nt = K >> 6;

    // 3-stage pipeline prologue: issue copies for tiles 0 and 1
#pragma unroll
    for (int j = 0; j < 4; j++) {
        cpa16(smBase + stsOff[j], Ag + j * 8);
        cpa16(smBase + 16384 + stsOff[j], Bg + j * 8);
    }
    cpa_commit();
    if (nt > 1) {
        const unsigned nbase = smBase + 32768;
#pragma unroll
        for (int j = 0; j < 4; j++) {
            cpa16(nbase + stsOff[j], Ag + 64 + j * 8);
            cpa16(nbase + 16384 + stsOff[j], Bg + 64 + j * 8);
        }
        cpa_commit();
    }

    int buf = 0;
    for (int t = 0; t < nt; t++) {
        if (t + 1 < nt) cpa_wait1(); else cpa_wait0();
        __syncthreads();
        if (t + 2 < nt) {
            int nb3 = buf + 2; if (nb3 >= 3) nb3 -= 3;
            const unsigned nbase = smBase + (unsigned)nb3 * 32768u;
            const __half* Agn = Ag + (size_t)(t + 2) * 64;
            const __half* Bgn = Bg + (size_t)(t + 2) * 64;
#pragma unroll
            for (int j = 0; j < 4; j++) {
                cpa16(nbase + stsOff[j], Agn + j * 8);
                cpa16(nbase + 16384 + stsOff[j], Bgn + j * 8);
            }
            cpa_commit();
        }
        const unsigned aT = smBase + (unsigned)buf * 32768u;
        const unsigned bT = aT + 16384;
#pragma unroll
        for (int kg = 0; kg < 4; kg++) {
            unsigned afr[2][4];
#pragma unroll
            for (int fm = 0; fm < 2; fm++) {
                int rr = aRow + fm * 16;
                unsigned ad = aT + (unsigned)(rr * 128 +
                               ((((kg << 1) + aQ) ^ (rr & 7)) << 4));
                ldsm4(afr[fm][0], afr[fm][1], afr[fm][2], afr[fm][3], ad);
            }
#pragma unroll
            for (int fp = 0; fp < 4; fp++) {
                int rr = bRow + fp * 16;
                unsigned bd = bT + (unsigned)(rr * 128 +
                               ((((kg << 1) + bQ) ^ (rr & 7)) << 4));
                unsigned b00, b01, b10, b11;
                ldsm4(b00, b01, b10, b11, bd);
                mma_f16(acc[0][2 * fp],     afr[0], b00, b01);
                mma_f16(acc[0][2 * fp + 1], afr[0], b10, b11);
                mma_f16(acc[1][2 * fp],     afr[1], b00, b01);
                mma_f16(acc[1][2 * fp + 1], afr[1], b10, b11);
            }
        }
        if (++buf == 3) buf = 0;
        if (t + 1 < nt) __syncthreads();   // all warps done with old buffer
    }

    const int crow = lane >> 2;
    const int ccol = (lane & 3) * 2;
    if (mode == 1) {
#pragma unroll
        for (int fm = 0; fm < 2; fm++) {
            int rr = rowBase + wm + fm * 16 + crow;
#pragma unroll
            for (int fn = 0; fn < 8; fn++) {
                int cc = colBase + wn + fn * 8 + ccol;
                float b0v = bias[cc], b1v = bias[cc + 1];
                float2 v0, v1;
                v0.x = fsigmoid(acc[fm][fn][0] + b0v);
                v0.y = fsigmoid(acc[fm][fn][1] + b1v);
                v1.x = fsigmoid(acc[fm][fn][2] + b0v);
                v1.y = fsigmoid(acc[fm][fn][3] + b1v);
                *(float2*)&C[(size_t)rr * NC + cc] = v0;
                *(float2*)&C[(size_t)(rr + 8) * NC + cc] = v1;
                if (Ch) {
                    *(__half2*)&Ch[(size_t)rr * NC + cc] = __floats2half2_rn(v0.x, v0.y);
                    *(__half2*)&Ch[(size_t)(rr + 8) * NC + cc] = __floats2half2_rn(v1.x, v1.y);
                }
            }
        }
    } else {
#pragma unroll
        for (int fm = 0; fm < 2; fm++) {
            int rr = rowBase + wm + fm * 16 + crow;
#pragma unroll
            for (int fn = 0; fn < 8; fn++) {
                int cc = colBase + wn + fn * 8 + ccol;
                float2 v0 = make_float2(acc[fm][fn][0], acc[fm][fn][1]);
                float2 v1 = make_float2(acc[fm][fn][2], acc[fm][fn][3]);
                *(float2*)&C[(size_t)rr * NC + cc] = v0;
                *(float2*)&C[(size_t)(rr + 8) * NC + cc] = v1;
            }
        }
        if (bi != bj) {
#pragma unroll
            for (int fm = 0; fm < 2; fm++) {
                int rr = rowBase + wm + fm * 16 + crow;
#pragma unroll
                for (int fn = 0; fn < 8; fn++) {
                    int cc = colBase + wn + fn * 8 + ccol;
                    C[(size_t)cc * NC + rr]           = acc[fm][fn][0];
                    C[(size_t)(cc + 1) * NC + rr]     = acc[fm][fn][1];
                    C[(size_t)cc * NC + rr + 8]       = acc[fm][fn][2];
                    C[(size_t)(cc + 1) * NC + rr + 8] = acc[fm][fn][3];
                }
            }
        }
        // fused prefix-min: d = SEN[i] + SEN[j] - 2*G[i,j] over j<i
        float senC[8][2];
#pragma unroll
        for (int fn = 0; fn < 8; fn++) {
            senC[fn][0] = sen[colBase + wn + fn * 8 + ccol];
            senC[fn][1] = sen[colBase + wn + fn * 8 + ccol + 1];
        }
        float rmin[2][2] = {{INFINITY, INFINITY}, {INFINITY, INFINITY}};
#pragma unroll
        for (int fm = 0; fm < 2; fm++) {
#pragma unroll
            for (int h = 0; h < 2; h++) {
                int lrow = wm + fm * 16 + crow + h * 8;
                float senR = sen[rowBase + lrow];
#pragma unroll
                for (int fn = 0; fn < 8; fn++) {
#pragma unroll
                    for (int c = 0; c < 2; c++) {
                        int lcol = wn + fn * 8 + ccol + c;
                        bool ok = (bi != bj) || (lcol < lrow);
                        if (ok) {
                            float d = senR + senC[fn][c]
                                    - 2.0f * acc[fm][fn][h * 2 + c];
                            rmin[fm][h] = fminf(rmin[fm][h], d);
                        }
                    }
                }
            }
        }
#pragma unroll
        for (int o = 1; o < 4; o <<= 1) {
#pragma unroll
            for (int fm = 0; fm < 2; fm++)
#pragma unroll
                for (int h = 0; h < 2; h++)
                    rmin[fm][h] = fminf(rmin[fm][h],
                        __shfl_xor_sync(0xffffffffu, rmin[fm][h], o));
        }
        if ((lane & 3) == 0) {
#pragma unroll
            for (int fm = 0; fm < 2; fm++)
#pragma unroll
                for (int h = 0; h < 2; h++) {
                    if (rmin[fm][h] < INFINITY) {
                        int gr = rowBase + wm + fm * 16 + crow + h * 8;
                        atomicMin(&mindu[gr], encf(rmin[fm][h]));
                    }
                }
        }
    }
}

// ---------------- standalone scan (layer 1) ----------------
__global__ void scan1_kernel(const float* G, const float* sen,
                             const unsigned* mindu, const float* base,
                             int* rules, int* protos, int* count, int N) {
    scan_block(G, sen, mindu, base, rules, protos, count, N);
}

// ---------------- final lamb (layer 1) ----------------
__global__ void lamb1_kernel(int N, float* __restrict__ out) {
    lamb_dev(blockIdx.x, g_G1, g_SEN[1], g_rules[1], g_protos[1],
             g_count[1], g_base[1][1], out, N);
}

// ---------------- host-side orchestration ----------------
extern "C" void kernel_launch(void* const* d_in, const int* in_sizes, int n_in,
                              void* d_out, int out_size) {
    const float* x  = (const float*)d_in[0];
    const float* W0 = (const float*)d_in[1];
    const float* b0 = (const float*)d_in[2];
    const float* W1 = (const float*)d_in[3];
    const float* b1 = (const float*)d_in[4];

    int DH   = in_sizes[2];            // 2048
    int DOUT = in_sizes[4];            // 1024
    int DIN  = in_sizes[1] / DH;       // 2048
    int N    = in_sizes[0] / DIN;      // 2048

    float* out   = (float*)d_out;
    float* outH  = out;
    float* lamb0 = out + (size_t)N * DOUT;
    float* lamb1 = lamb0 + N;

    float *G0p, *G1p, *Hp, *SENp, *basep;
    __half *Ahp, *Bhp, *Hhp;
    unsigned* mindup;
    int *rulesp, *protosp, *countp;
    cudaGetSymbolAddress((void**)&G0p, g_G0);
    cudaGetSymbolAddress((void**)&G1p, g_G1);
    cudaGetSymbolAddress((void**)&Hp, g_H);
    cudaGetSymbolAddress((void**)&Ahp, g_Ah);
    cudaGetSymbolAddress((void**)&Bhp, g_Bh);
    cudaGetSymbolAddress((void**)&Hhp, g_Hh);
    cudaGetSymbolAddress((void**)&SENp, g_SEN);
    cudaGetSymbolAddress((void**)&basep, g_base);
    cudaGetSymbolAddress((void**)&mindup, g_mindu);
    cudaGetSymbolAddress((void**)&rulesp, g_rules);
    cudaGetSymbolAddress((void**)&protosp, g_protos);
    cudaGetSymbolAddress((void**)&countp, g_count);

    float* SEN0 = SENp;            float* SEN1 = SENp + MAXN;
    float* base0 = basep;          float* base1 = basep + 2;
    unsigned* mind0 = mindup;      unsigned* mind1 = mindup + MAXN;
    int* rules0 = rulesp;          int* rules1 = rulesp + MAXN;
    int* protos0 = protosp;        int* protos1 = protosp + MAXN;
    int* count0 = countp;          int* count1 = countp + 1;

    cudaFuncSetAttribute(mega_gemm_kernel,
                         cudaFuncAttributeMaxDynamicSharedMemorySize, GEMM_SMEM);

    const int tri = (N / 128) * (N / 128 + 1) / 2;   // 136

    // 1) aux0: mindinit0 || rowstats(x -> Ah, SEN0) || convert W0->Bh || colsum(x)
    {
        int grid = (N >> 8) + N + NCONV + (DIN >> 8) * NCHUNK;
        fused_aux_kernel<<<grid, 256>>>(
            x, Ahp, N, DIN, W0, Bhp, DH, SEN0, mind0,
            nullptr, nullptr, nullptr, nullptr, nullptr, nullptr, nullptr, 0);
    }
    // 2) MEGA0: gram0 (Ah->G0, mind0) || lin0 (Ah,Bh->H,Hh) || base0 role
    {
        int grid = tri + (N / 128) * (DH / 128) + 0 + 1;
        mega_gemm_kernel<<<grid, 256, GEMM_SMEM>>>(
            Ahp, G0p, N, DIN, SEN0, mind0, tri,
            Ahp, Bhp, Hp, Hhp, b0, DH, DIN, base0,
            nullptr, nullptr, nullptr, nullptr, nullptr, nullptr, nullptr, 0);
    }
    // 3) aux1: scan0 || mindinit1 || rowstats(H -> SEN1) || convert W1->Bh || colsum(H)
    {
        int grid = 1 + (N >> 8) + N + NCONV + (DH >> 8) * NCHUNK;
        fused_aux_kernel<<<grid, 256>>>(
            Hp, nullptr, N, DH, W1, Bhp, DOUT, SEN1, mind1,
            G0p, SEN0, mind0, base0, rules0, protos0, count0, N);
    }
    // 4) MEGA1: gram1 (Hh->G1, mind1) || lin1 (Hh,Bh->outH) || lamb0 || base1
    {
        int grid = tri + (N / 128) * (DOUT / 128) + N + 1;
        mega_gemm_kernel<<<grid, 256, GEMM_SMEM>>>(
            Hhp, G1p, N, DH, SEN1, mind1, tri,
            Hhp, Bhp, outH, nullptr, b1, DOUT, DH, base1,
            G0p, SEN0, base0, rules0, protos0, count0, lamb0, N);
    }
    // 5) scan1 (parallel-certs fast path)
    scan1_kernel<<<1, 256>>>(G1p, SEN1, mind1, base1,
                             rules1, protos1, count1, N);
    // 6) lamb1
    lamb1_kernel<<<N, 256>>>(N, lamb1);
}

// round 16
// speedup vs baseline: 1.0572x; 1.0572x over previous
#include <cuda_runtime.h>
#include <cuda_fp16.h>
#include <math.h>
#include <stdint.h>

// SOMFNN: two layers of (ALMMo codebook lamb) + sigmoid(Linear)
// stau = base/2 (scalar); prototypes are input samples -> all distances from
// Gram = X X^T; min-distance-over-all-predecessors shortcut for new rules.
// GEMMs: fp16 mma.sync.m16n8k16 (fp32 accum), SW128-swizzled smem, 2-stage
// cp.async (r14). r16: layer-1 stats computed from fp16 Hh (consistent with
// G1); f32 H eliminated (16MB stores + 16MB reads gone). GEMM core untouched.

#define MAXN 2048
#define MAXD 2048
#define NCHUNK 32
#define NCONV 512
#define GEMM_SMEM 65536

__device__ float g_G0[(size_t)MAXN * MAXN];
__device__ float g_G1[(size_t)MAXN * MAXN];
__device__ __half g_Ah[(size_t)MAXN * MAXD];
__device__ __half g_Bh[(size_t)MAXN * MAXD];
__device__ __half g_Hh[(size_t)MAXN * MAXD];
__device__ float g_SEN[2][MAXN];
__device__ float g_colpart[NCHUNK][MAXD];
__device__ float g_base[2][2];
__device__ unsigned g_mindu[2][MAXN];
__device__ int   g_rules[2][MAXN];
__device__ int   g_protos[2][MAXN];
__device__ int   g_count[2];

// order-preserving float<->unsigned encoding (monotone; min exact)
__device__ __forceinline__ unsigned encf(float f) {
    unsigned u = __float_as_uint(f);
    return (u & 0x80000000u) ? ~u : (u | 0x80000000u);
}
__device__ __forceinline__ float decf(unsigned e) {
    unsigned u = (e & 0x80000000u) ? (e ^ 0x80000000u) : ~e;
    return __uint_as_float(u);
}

__device__ __forceinline__ float blockReduceSum(float v) {
    __shared__ float sh[32];
    int lane = threadIdx.x & 31, wid = threadIdx.x >> 5;
#pragma unroll
    for (int o = 16; o; o >>= 1) v += __shfl_down_sync(0xffffffffu, v, o);
    __syncthreads();
    if (lane == 0) sh[wid] = v;
    __syncthreads();
    if (wid == 0) {
        int nw = (blockDim.x + 31) >> 5;
        v = (lane < nw) ? sh[lane] : 0.0f;
#pragma unroll
        for (int o = 16; o; o >>= 1) v += __shfl_down_sync(0xffffffffu, v, o);
    }
    return v;
}

// ---------------- sequential rule-creation scan (device fn, 1 warp) --------
__device__ void scan_dev(const float* G, const float* sen,
                         const unsigned* mindu, const float* base,
                         int* rules, int* protos, int* count, int N) {
    const int lane = threadIdx.x & 31;
    const float DELTA = 0.13533528323661270f;  // exp(-2)
    float stau = base[1];
    bool st_ok = (stau > 0.0f) && (stau < 3.0e38f);
    float thr2 = 2.0f * stau;
    int cnt = 0;

    for (int i0 = 0; i0 < N; i0 += 32) {
        int lim = (N - i0 < 32) ? (N - i0) : 32;
        int myi = i0 + lane;
        bool cert = false;
        if (myi < N && st_ok)
            cert = (decf(mindu[myi]) > thr2);   // exp(-mind/stau) < e^-2
        unsigned mask = __ballot_sync(0xffffffffu, cert);
        unsigned need = (lim == 32) ? 0xffffffffu : ((1u << lim) - 1u);
        if ((mask & need) == need) {
            if (lane < lim) {
                rules[myi] = cnt + lane;
                protos[cnt + lane] = myi;
            }
            cnt += lim;
            continue;
        }
        for (int t = 0; t < lim; t++) {
            int i = i0 + t;
            bool newr;
            int slot = 0;
            if (cnt == 0 || ((mask >> t) & 1u)) {
                newr = true;
            } else {
                float si = sen[i];
                const float* Gi = G + (size_t)i * N;
                float best = -INFINITY;
                int bestr = 0x7fffffff;
                for (int rr = lane; rr < cnt; rr += 32) {
                    int pr = protos[rr];
                    float dd = si + sen[pr] - 2.0f * Gi[pr];
                    float dens = __expf(-dd / stau);
                    if (dens > best) { best = dens; bestr = rr; }
                }
#pragma unroll
                for (int off = 16; off; off >>= 1) {
                    float ob = __shfl_down_sync(0xffffffffu, best, off);
                    int obr = __shfl_down_sync(0xffffffffu, bestr, off);
                    if (ob > best || (ob == best && obr < bestr)) { best = ob; bestr = obr; }
                }
                best  = __shfl_sync(0xffffffffu, best, 0);
                bestr = __shfl_sync(0xffffffffu, bestr, 0);
                newr = (best < DELTA);
                slot = bestr;
            }
            if (newr) slot = cnt;
            if (lane == 0) rules[i] = slot;
            if (newr) {
                if (lane == 0) protos[cnt] = i;
                cnt++;
            }
        }
    }
    if (lane == 0) count[0] = cnt;
}

// ---------------- block-level scan with parallel-certs fast path ------------
__device__ void scan_block(const float* G, const float* sen,
                           const unsigned* mindu, const float* base,
                           int* rules, int* protos, int* count, int N) {
    __shared__ int anyfail;
    const int tid = threadIdx.x;
    float stau = base[1];
    bool st_ok = (stau > 0.0f) && (stau < 3.0e38f);
    float thr2 = 2.0f * stau;
    if (tid == 0) anyfail = 0;
    __syncthreads();
    for (int i = tid; i < N; i += 256) {
        bool cert = st_ok && (decf(mindu[i]) > thr2);
        if (!cert) anyfail = 1;
    }
    __syncthreads();
    if (!anyfail) {
        for (int i = tid; i < N; i += 256) {
            rules[i] = i;
            protos[i] = i;
        }
        if (tid == 0) count[0] = N;
    } else if (tid < 32) {
        scan_dev(G, sen, mindu, base, rules, protos, count, N);
    }
}

// ---------------- fused aux kernel (role-split grid) -------------------------
// role order: [scan prev (0/1)] [mindinit] [rowstats f32 or fp16]
//             [convert W] [colsum f32 or fp16]
__global__ void fused_aux_kernel(
    const float* __restrict__ X, const __half* __restrict__ XH,
    __half* __restrict__ Xh, int N, int K,
    const float* __restrict__ W, __half* __restrict__ Wh, int WM,
    float* __restrict__ sen, unsigned* __restrict__ minduInit,
    const float* Gprev, const float* senPrev, const unsigned* minduPrev,
    const float* basePrev, int* rulesPrev, int* protosPrev, int* countPrev,
    int Nprev)
{
    int bid = blockIdx.x;
    const int tid = threadIdx.x;

    const int nScan = Gprev ? 1 : 0;
    if (bid < nScan) {
        scan_block(Gprev, senPrev, minduPrev, basePrev,
                   rulesPrev, protosPrev, countPrev, Nprev);
        return;
    }
    bid -= nScan;

    const int nMind = N >> 8;
    if (bid < nMind) {
        minduInit[bid * 256 + tid] = 0xFF800000u;   // encf(+inf)
        return;
    }
    bid -= nMind;

    if (bid < N) {   // rowstats: one block per row
        float s = 0.0f;
        if (X) {     // f32 input: optional fp16 convert-out + sumsq
            const float4* row = (const float4*)(X + (size_t)bid * K);
            __half2* drow = Xh ? (__half2*)(Xh + (size_t)bid * K) : nullptr;
            const int k4 = K >> 2;
#pragma unroll 4
            for (int k = tid; k < k4; k += 256) {
                float4 v = row[k];
                s += v.x * v.x + v.y * v.y + v.z * v.z + v.w * v.w;
                if (drow) {
                    drow[2 * k]     = __floats2half2_rn(v.x, v.y);
                    drow[2 * k + 1] = __floats2half2_rn(v.z, v.w);
                }
            }
        } else {     // fp16 input: sumsq of the exact values the GEMM uses
            const uint4* row = (const uint4*)(XH + (size_t)bid * K);
            const int k8 = K >> 3;
#pragma unroll 2
            for (int k = tid; k < k8; k += 256) {
                uint4 u = row[k];
                float2 p0 = __half22float2(*(__half2*)&u.x);
                float2 p1 = __half22float2(*(__half2*)&u.y);
                float2 p2 = __half22float2(*(__half2*)&u.z);
                float2 p3 = __half22float2(*(__half2*)&u.w);
                s += p0.x * p0.x + p0.y * p0.y + p1.x * p1.x + p1.y * p1.y;
                s += p2.x * p2.x + p2.y * p2.y + p3.x * p3.x + p3.y * p3.y;
            }
        }
        s = blockReduceSum(s);
        if (tid == 0) sen[bid] = s;
        return;
    }
    bid -= N;

    const int nConvW = Wh ? NCONV : 0;
    if (bid < nConvW) {
        int n4 = (WM * K) >> 2;
#pragma unroll 2
        for (int i = bid * 256 + tid; i < n4; i += nConvW * 256) {
            float4 v = ((const float4*)W)[i];
            __half2* d = (__half2*)Wh + 2 * i;
            d[0] = __floats2half2_rn(v.x, v.y);
            d[1] = __floats2half2_rn(v.z, v.w);
        }
        return;
    }
    bid -= nConvW;

    {   // colsum chunks, 4-row unroll (same summation order)
        int chunk = bid / (K >> 8);
        int cseg = bid % (K >> 8);
        int c = cseg * 256 + tid;
        int r0 = chunk * (N / NCHUNK), r1 = r0 + N / NCHUNK;
        float s = 0.0f;
        if (X) {
            int i = r0;
            for (; i + 4 <= r1; i += 4) {
                float a0 = X[(size_t)i * K + c];
                float a1 = X[(size_t)(i + 1) * K + c];
                float a2 = X[(size_t)(i + 2) * K + c];
                float a3 = X[(size_t)(i + 3) * K + c];
                s += a0; s += a1; s += a2; s += a3;
            }
            for (; i < r1; i++) s += X[(size_t)i * K + c];
        } else {
            int i = r0;
            for (; i + 4 <= r1; i += 4) {
                float a0 = __half2float(XH[(size_t)i * K + c]);
                float a1 = __half2float(XH[(size_t)(i + 1) * K + c]);
                float a2 = __half2float(XH[(size_t)(i + 2) * K + c]);
                float a3 = __half2float(XH[(size_t)(i + 3) * K + c]);
                s += a0; s += a1; s += a2; s += a3;
            }
            for (; i < r1; i++) s += __half2float(XH[(size_t)i * K + c]);
        }
        g_colpart[chunk][c] = s;
    }
}

// ---------------- tensor-core helpers ----------------
__device__ __forceinline__ unsigned smaddr(const void* p) {
    unsigned r;
    asm("{.reg .u64 t; cvta.to.shared.u64 t, %1; cvt.u32.u64 %0, t;}"
        : "=r"(r) : "l"(p));
    return r;
}

__device__ __forceinline__ void ldsm4(unsigned& r0, unsigned& r1, unsigned& r2,
                                      unsigned& r3, unsigned a) {
    asm volatile("ldmatrix.sync.aligned.m8n8.x4.shared.b16 {%0,%1,%2,%3},[%4];"
                 : "=r"(r0), "=r"(r1), "=r"(r2), "=r"(r3) : "r"(a));
}

__device__ __forceinline__ void mma_f16(float* c, const unsigned* a,
                                        unsigned b0, unsigned b1) {
    asm volatile(
        "mma.sync.aligned.m16n8k16.row.col.f32.f16.f16.f32 "
        "{%0,%1,%2,%3},{%4,%5,%6,%7},{%8,%9},{%0,%1,%2,%3};"
        : "+f"(c[0]), "+f"(c[1]), "+f"(c[2]), "+f"(c[3])
        : "r"(a[0]), "r"(a[1]), "r"(a[2]), "r"(a[3]), "r"(b0), "r"(b1));
}

__device__ __forceinline__ void cpa16(unsigned dst, const void* src) {
    asm volatile("cp.async.cg.shared.global [%0], [%1], 16;"
                 :: "r"(dst), "l"(src));
}
__device__ __forceinline__ void cpa_commit() {
    asm volatile("cp.async.commit_group;");
}
__device__ __forceinline__ void cpa_wait0() {
    asm volatile("cp.async.wait_group 0;");
}

__device__ __forceinline__ float fsigmoid(float s) {
    return 1.0f / (1.0f + __expf(-s));
}

// ---------------- lamb (density normalization) device fn -------------------
__device__ void lamb_dev(int n, const float* G, const float* sen,
                         const int* rules, const int* protos, int count,
                         float stau, float* out, int N) {
    float sn = sen[n];
    float inv = -1.0f / stau;
    const float* Gn = G + (size_t)n * N;
    float s = 0.0f;
    for (int r = threadIdx.x; r < count; r += blockDim.x) {
        int pr = protos[r];
        float d = sn + sen[pr] - 2.0f * Gn[pr];
        s += __expf(d * inv);
    }
    s = blockReduceSum(s);
    if (threadIdx.x == 0) {
        int pr = protos[rules[n]];
        float d = sn + sen[pr] - 2.0f * Gn[pr];
        out[n] = __expf(d * inv) / s;
    }
}

// ---------------- base role (1 block, 256 threads) -------------------------
__device__ void base_dev(const float* sen, float* baseout, int N, int K) {
    float invN = 1.0f / (float)N;
    float s1 = 0.0f, s2 = 0.0f;
    for (int i = threadIdx.x; i < N; i += 256) s1 += sen[i];
    for (int c = threadIdx.x; c < K; c += 256) {
        float cs = 0.0f;
#pragma unroll
        for (int h = 0; h < NCHUNK; h++) cs += g_colpart[h][c];
        float m = cs * invN;
        s2 += m * m;
    }
    s1 = blockReduceSum(s1);
    __syncthreads();
    s2 = blockReduceSum(s2);
    if (threadIdx.x == 0) {
        float base = s1 * invN - s2;
        baseout[0] = base;
        baseout[1] = 0.5f * base;
    }
}

// ---------------- MEGA GEMM: gram || linear || lamb(prev) || base ----------
__global__ void __launch_bounds__(256, 2)
mega_gemm_kernel(const __half* __restrict__ Agr, float* __restrict__ G,
                 int Ng, int Kg, const float* __restrict__ sen,
                 unsigned* __restrict__ mindu, int triCount,
                 const __half* __restrict__ Al, const __half* __restrict__ Bl,
                 float* __restrict__ Cl, __half* __restrict__ Chl,
                 const float* __restrict__ bias, int Nl, int Kl,
                 float* __restrict__ baseOut,
                 const float* __restrict__ lambG,
                 const float* __restrict__ lambSen,
                 const float* __restrict__ lambBase,
                 const int* __restrict__ lambRules,
                 const int* __restrict__ lambProtos,
                 const int* __restrict__ lambCount,
                 float* __restrict__ lambOut, int lambN) {
    extern __shared__ char sm[];
    const int tid = threadIdx.x, wid = tid >> 5, lane = tid & 31;

    const int linCount = (Ng >> 7) * (Nl >> 7);
    const int nb = triCount + linCount;
    if ((int)blockIdx.x == nb + lambN) {
        base_dev(sen, baseOut, Ng, Kg);   // base for CURRENT layer
        return;
    }
    if ((int)blockIdx.x >= nb) {
        int n = blockIdx.x - nb;
        lamb_dev(n, lambG, lambSen, lambRules, lambProtos, lambCount[0],
                 lambBase[1], lambOut, lambN);
        return;
    }

    const __half *A, *B;
    float* C;
    __half* Ch;
    int NC, K, mode, bi, bj;
    if ((int)blockIdx.x < triCount) {
        int id = blockIdx.x;
        bi = (int)((sqrtf(8.0f * (float)id + 1.0f) - 1.0f) * 0.5f);
        while ((bi + 1) * (bi + 2) / 2 <= id) bi++;
        while (bi * (bi + 1) / 2 > id) bi--;
        bj = id - bi * (bi + 1) / 2;
        A = Agr; B = Agr; C = G; Ch = nullptr; NC = Ng; K = Kg; mode = 2;
    } else {
        int lid = blockIdx.x - triCount;
        int nbx = Nl >> 7;
        bi = lid / nbx; bj = lid % nbx;
        A = Al; B = Bl; C = Cl; Ch = Chl; NC = Nl; K = Kl; mode = 1;
    }
    const int rowBase = bi << 7, colBase = bj << 7;

    const int r = tid >> 1;
    const int hh = tid & 1;
    const __half* Ag = A + (size_t)(rowBase + r) * K + hh * 32;
    const __half* Bg = B + (size_t)(colBase + r) * K + hh * 32;
    unsigned stsOff[4];
#pragma unroll
    for (int j = 0; j < 4; j++)
        stsOff[j] = (unsigned)(r * 128 + ((((hh << 2) + j) ^ (r & 7)) << 4));

    const int wm = (wid & 3) << 5, wn = (wid >> 2) << 6;
    const int aRow = wm + ((lane >> 3) & 1) * 8 + (lane & 7);
    const int aQ = lane >> 4;
    const int bRow = wn + (lane >> 4) * 8 + (lane & 7);
    const int bQ = (lane >> 3) & 1;

    const unsigned smBase = smaddr(sm);

    float acc[2][8][4];
#pragma unroll
    for (int fm = 0; fm < 2; fm++)
#pragma unroll
        for (int fn = 0; fn < 8; fn++)
#pragma unroll
            for (int q = 0; q < 4; q++) acc[fm][fn][q] = 0.0f;

    // preload tile 0 via cp.async (GMEM -> SMEM, no register round-trip)
#pragma unroll
    for (int j = 0; j < 4; j++) {
        cpa16(smBase + stsOff[j], Ag + j * 8);
        cpa16(smBase + 16384 + stsOff[j], Bg + j * 8);
    }
    cpa_commit();
    cpa_wait0();
    __syncthreads();

    const int nt = K >> 6;
    int buf = 0;
    for (int t = 0; t < nt; t++) {
        if (t + 1 < nt) {
            const unsigned nbase = smBase + (buf ^ 1) * 32768;
            const __half* Agn = Ag + (size_t)(t + 1) * 64;
            const __half* Bgn = Bg + (size_t)(t + 1) * 64;
#pragma unroll
            for (int j = 0; j < 4; j++) {
                cpa16(nbase + stsOff[j], Agn + j * 8);
                cpa16(nbase + 16384 + stsOff[j], Bgn + j * 8);
            }
            cpa_commit();
        }
        const unsigned aT = smBase + buf * 32768;
        const unsigned bT = aT + 16384;
#pragma unroll
        for (int kg = 0; kg < 4; kg++) {
            unsigned afr[2][4];
#pragma unroll
            for (int fm = 0; fm < 2; fm++) {
                int rr = aRow + fm * 16;
                unsigned ad = aT + (unsigned)(rr * 128 +
                               ((((kg << 1) + aQ) ^ (rr & 7)) << 4));
                ldsm4(afr[fm][0], afr[fm][1], afr[fm][2], afr[fm][3], ad);
            }
#pragma unroll
            for (int fp = 0; fp < 4; fp++) {
                int rr = bRow + fp * 16;
                unsigned bd = bT + (unsigned)(rr * 128 +
                               ((((kg << 1) + bQ) ^ (rr & 7)) << 4));
                unsigned b00, b01, b10, b11;
                ldsm4(b00, b01, b10, b11, bd);
                mma_f16(acc[0][2 * fp],     afr[0], b00, b01);
                mma_f16(acc[0][2 * fp + 1], afr[0], b10, b11);
                mma_f16(acc[1][2 * fp],     afr[1], b00, b01);
                mma_f16(acc[1][2 * fp + 1], afr[1], b10, b11);
            }
        }
        if (t + 1 < nt) {
            cpa_wait0();
            __syncthreads();
            buf ^= 1;
        }
    }

    const int crow = lane >> 2;
    const int ccol = (lane & 3) * 2;
    if (mode == 1) {
#pragma unroll
        for (int fm = 0; fm < 2; fm++) {
            int rr = rowBase + wm + fm * 16 + crow;
#pragma unroll
            for (int fn = 0; fn < 8; fn++) {
                int cc = colBase + wn + fn * 8 + ccol;
                float b0v = bias[cc], b1v = bias[cc + 1];
                float2 v0, v1;
                v0.x = fsigmoid(acc[fm][fn][0] + b0v);
                v0.y = fsigmoid(acc[fm][fn][1] + b1v);
                v1.x = fsigmoid(acc[fm][fn][2] + b0v);
                v1.y = fsigmoid(acc[fm][fn][3] + b1v);
                if (C) {
                    *(float2*)&C[(size_t)rr * NC + cc] = v0;
                    *(float2*)&C[(size_t)(rr + 8) * NC + cc] = v1;
                }
                if (Ch) {
                    *(__half2*)&Ch[(size_t)rr * NC + cc] = __floats2half2_rn(v0.x, v0.y);
                    *(__half2*)&Ch[(size_t)(rr + 8) * NC + cc] = __floats2half2_rn(v1.x, v1.y);
                }
            }
        }
    } else {
#pragma unroll
        for (int fm = 0; fm < 2; fm++) {
            int rr = rowBase + wm + fm * 16 + crow;
#pragma unroll
            for (int fn = 0; fn < 8; fn++) {
                int cc = colBase + wn + fn * 8 + ccol;
                float2 v0 = make_float2(acc[fm][fn][0], acc[fm][fn][1]);
                float2 v1 = make_float2(acc[fm][fn][2], acc[fm][fn][3]);
                *(float2*)&C[(size_t)rr * NC + cc] = v0;
                *(float2*)&C[(size_t)(rr + 8) * NC + cc] = v1;
            }
        }
        if (bi != bj) {
#pragma unroll
            for (int fm = 0; fm < 2; fm++) {
                int rr = rowBase + wm + fm * 16 + crow;
#pragma unroll
                for (int fn = 0; fn < 8; fn++) {
                    int cc = colBase + wn + fn * 8 + ccol;
                    C[(size_t)cc * NC + rr]           = acc[fm][fn][0];
                    C[(size_t)(cc + 1) * NC + rr]     = acc[fm][fn][1];
                    C[(size_t)cc * NC + rr + 8]       = acc[fm][fn][2];
                    C[(size_t)(cc + 1) * NC + rr + 8] = acc[fm][fn][3];
                }
            }
        }
        // fused prefix-min: d = SEN[i] + SEN[j] - 2*G[i,j] over j<i
        float senC[8][2];
#pragma unroll
        for (int fn = 0; fn < 8; fn++) {
            senC[fn][0] = sen[colBase + wn + fn * 8 + ccol];
            senC[fn][1] = sen[colBase + wn + fn * 8 + ccol + 1];
        }
        float rmin[2][2] = {{INFINITY, INFINITY}, {INFINITY, INFINITY}};
#pragma unroll
        for (int fm = 0; fm < 2; fm++) {
#pragma unroll
            for (int h = 0; h < 2; h++) {
                int lrow = wm + fm * 16 + crow + h * 8;
                float senR = sen[rowBase + lrow];
#pragma unroll
                for (int fn = 0; fn < 8; fn++) {
#pragma unroll
                    for (int c = 0; c < 2; c++) {
                        int lcol = wn + fn * 8 + ccol + c;
                        bool ok = (bi != bj) || (lcol < lrow);
                        if (ok) {
                            float d = senR + senC[fn][c]
                                    - 2.0f * acc[fm][fn][h * 2 + c];
                            rmin[fm][h] = fminf(rmin[fm][h], d);
                        }
                    }
                }
            }
        }
#pragma unroll
        for (int o = 1; o < 4; o <<= 1) {
#pragma unroll
            for (int fm = 0; fm < 2; fm++)
#pragma unroll
                for (int h = 0; h < 2; h++)
                    rmin[fm][h] = fminf(rmin[fm][h],
                        __shfl_xor_sync(0xffffffffu, rmin[fm][h], o));
        }
        if ((lane & 3) == 0) {
#pragma unroll
            for (int fm = 0; fm < 2; fm++)
#pragma unroll
                for (int h = 0; h < 2; h++) {
                    if (rmin[fm][h] < INFINITY) {
                        int gr = rowBase + wm + fm * 16 + crow + h * 8;
                        atomicMin(&mindu[gr], encf(rmin[fm][h]));
                    }
                }
        }
    }
}

// ---------------- standalone scan (layer 1) ----------------
__global__ void scan1_kernel(const float* G, const float* sen,
                             const unsigned* mindu, const float* base,
                             int* rules, int* protos, int* count, int N) {
    scan_block(G, sen, mindu, base, rules, protos, count, N);
}

// ---------------- final lamb (layer 1) ----------------
__global__ void lamb1_kernel(int N, float* __restrict__ out) {
    lamb_dev(blockIdx.x, g_G1, g_SEN[1], g_rules[1], g_protos[1],
             g_count[1], g_base[1][1], out, N);
}

// ---------------- host-side orchestration ----------------
extern "C" void kernel_launch(void* const* d_in, const int* in_sizes, int n_in,
                              void* d_out, int out_size) {
    const float* x  = (const float*)d_in[0];
    const float* W0 = (const float*)d_in[1];
    const float* b0 = (const float*)d_in[2];
    const float* W1 = (const float*)d_in[3];
    const float* b1 = (const float*)d_in[4];

    int DH   = in_sizes[2];            // 2048
    int DOUT = in_sizes[4];            // 1024
    int DIN  = in_sizes[1] / DH;       // 2048
    int N    = in_sizes[0] / DIN;      // 2048

    float* out   = (float*)d_out;
    float* outH  = out;
    float* lamb0 = out + (size_t)N * DOUT;
    float* lamb1 = lamb0 + N;

    float *G0p, *G1p, *SENp, *basep;
    __half *Ahp, *Bhp, *Hhp;
    unsigned* mindup;
    int *rulesp, *protosp, *countp;
    cudaGetSymbolAddress((void**)&G0p, g_G0);
    cudaGetSymbolAddress((void**)&G1p, g_G1);
    cudaGetSymbolAddress((void**)&Ahp, g_Ah);
    cudaGetSymbolAddress((void**)&Bhp, g_Bh);
    cudaGetSymbolAddress((void**)&Hhp, g_Hh);
    cudaGetSymbolAddress((void**)&SENp, g_SEN);
    cudaGetSymbolAddress((void**)&basep, g_base);
    cudaGetSymbolAddress((void**)&mindup, g_mindu);
    cudaGetSymbolAddress((void**)&rulesp, g_rules);
    cudaGetSymbolAddress((void**)&protosp, g_protos);
    cudaGetSymbolAddress((void**)&countp, g_count);

    float* SEN0 = SENp;            float* SEN1 = SENp + MAXN;
    float* base0 = basep;          float* base1 = basep + 2;
    unsigned* mind0 = mindup;      unsigned* mind1 = mindup + MAXN;
    int* rules0 = rulesp;          int* rules1 = rulesp + MAXN;
    int* protos0 = protosp;        int* protos1 = protosp + MAXN;
    int* count0 = countp;          int* count1 = countp + 1;

    cudaFuncSetAttribute(mega_gemm_kernel,
                         cudaFuncAttributeMaxDynamicSharedMemorySize, GEMM_SMEM);

    const int tri = (N / 128) * (N / 128 + 1) / 2;   // 136

    // 1) aux0: mindinit0 || rowstats(x -> Ah, SEN0) || convert W0->Bh || colsum(x)
    {
        int grid = (N >> 8) + N + NCONV + (DIN >> 8) * NCHUNK;
        fused_aux_kernel<<<grid, 256>>>(
            x, nullptr, Ahp, N, DIN, W0, Bhp, DH, SEN0, mind0,
            nullptr, nullptr, nullptr, nullptr, nullptr, nullptr, nullptr, 0);
    }
    // 2) MEGA0: gram0 (Ah->G0, mind0) || lin0 (Ah,Bh -> Hh only) || base0 role
    {
        int grid = tri + (N / 128) * (DH / 128) + 0 + 1;
        mega_gemm_kernel<<<grid, 256, GEMM_SMEM>>>(
            Ahp, G0p, N, DIN, SEN0, mind0, tri,
            Ahp, Bhp, nullptr, Hhp, b0, DH, DIN, base0,
            nullptr, nullptr, nullptr, nullptr, nullptr, nullptr, nullptr, 0);
    }
    // 3) aux1: scan0 || mindinit1 || rowstats(Hh -> SEN1) || convert W1->Bh
    //          || colsum(Hh)
    {
        int grid = 1 + (N >> 8) + N + NCONV + (DH >> 8) * NCHUNK;
        fused_aux_kernel<<<grid, 256>>>(
            nullptr, Hhp, nullptr, N, DH, W1, Bhp, DOUT, SEN1, mind1,
            G0p, SEN0, mind0, base0, rules0, protos0, count0, N);
    }
    // 4) MEGA1: gram1 (Hh->G1, mind1) || lin1 (Hh,Bh->outH) || lamb0 || base1
    {
        int grid = tri + (N / 128) * (DOUT / 128) + N + 1;
        mega_gemm_kernel<<<grid, 256, GEMM_SMEM>>>(
            Hhp, G1p, N, DH, SEN1, mind1, tri,
            Hhp, Bhp, outH, nullptr, b1, DOUT, DH, base1,
            G0p, SEN0, base0, rules0, protos0, count0, lamb0, N);
    }
    // 5) scan1 (parallel-certs fast path)
    scan1_kernel<<<1, 256>>>(G1p, SEN1, mind1, base1,
                             rules1, protos1, count1, N);
    // 6) lamb1
    lamb1_kernel<<<N, 256>>>(N, lamb1);
}